// round 1
// baseline (speedup 1.0000x reference)
#include <cuda_runtime.h>
#include <cstdint>

// Problem constants (fixed shapes: B=8, H=W=512)
#define BB 8
#define NN (512*512)          // 262144 pixels per batch row
#define PP (BB*NN)            // 2,097,152 total pixels
#define THREADS 256
#define ITEMS 8
#define TILE (THREADS*ITEMS)  // 2048
#define BLKX (NN/TILE)        // 128 blocks per row
#define EQCAP 2048

// ---------------- device scratch (static, no allocations) ----------------
__device__ uint32_t g_keys[PP];              // 8 MB  monotone-mapped loss keys
__device__ float    g_loss3[PP];             // 8 MB  per-pixel loss_3
__device__ uint32_t g_hist[BB*256];
__device__ uint32_t g_prefix[BB];
__device__ int      g_kneed[BB];
__device__ int      g_eqcount[BB];
__device__ int      g_eqlist[BB*EQCAP];
__device__ double   g_sum_l3;
__device__ unsigned long long g_sum_tsel;
__device__ unsigned long long g_ttotal;

// monotone float -> uint mapping (order-preserving)
__device__ __forceinline__ uint32_t f2mono(float f) {
    uint32_t u = __float_as_uint(f);
    return (u & 0x80000000u) ? ~u : (u | 0x80000000u);
}

// Robust scalar read: harness may pass python floats as f32 or f64.
// For values in (0,1) (forget_rate=0.2, kdweight=0.1) the low 4 bytes of the
// f64 encoding reinterpret as a value NOT in (1e-6, 1), so this disambiguates.
__device__ __forceinline__ double read_scalar(const void* p) {
    float f = *(const float*)p;
    if (f > 1e-6f && f < 1.0f) return (double)f;
    return *(const double*)p;
}

// 2-class log-softmax + probs
__device__ __forceinline__ void sm2(float x0, float x1,
                                    float& lp0, float& lp1, float& p0, float& p1) {
    float m  = fmaxf(x0, x1);
    float e0 = __expf(x0 - m);
    float e1 = __expf(x1 - m);
    float s  = e0 + e1;
    float ls = __logf(s);
    float r  = __fdividef(1.0f, s);
    lp0 = x0 - m - ls;
    lp1 = x1 - m - ls;
    p0  = e0 * r;
    p1  = e1 * r;
}

// ---------------- kernels ----------------

__global__ void k_init(const void* forget) {
    int tid = threadIdx.x;
    double rem = 1.0 - read_scalar(forget);
    int num_rem = (int)(rem * (double)NN);
    if (tid < BB) {
        g_kneed[tid]   = num_rem;
        g_prefix[tid]  = 0u;
        g_eqcount[tid] = 0;
    }
    if (tid == 0) {
        g_sum_l3   = 0.0;
        g_sum_tsel = 0ull;
        g_ttotal   = 0ull;
    }
    for (int i = tid; i < BB*256; i += blockDim.x) g_hist[i] = 0u;
}

// Fused: loss math + key/loss3 store + pass-0 histogram + targets total sum
__global__ void __launch_bounds__(THREADS)
k_compute(const float* __restrict__ in1, const float* __restrict__ in2,
          const float* __restrict__ in3, const int* __restrict__ tgt,
          const void* __restrict__ kdw_p)
{
    __shared__ uint32_t sh[256];
    int tid = threadIdx.x;
    sh[tid] = 0u;
    __syncthreads();

    const int row = blockIdx.y;
    const float kdw = (float)read_scalar(kdw_p);
    const float w   = 1.0f - kdw;

    const float* b1 = in1 + (size_t)row * 2 * NN;
    const float* b2 = in2 + (size_t)row * 2 * NN;
    const float* b3 = in3 + (size_t)row * 2 * NN;
    const int*   bt = tgt + (size_t)row * NN;

    int ri0 = blockIdx.x * TILE + tid;
    int tcnt = 0;

#pragma unroll
    for (int it = 0; it < ITEMS; it++) {
        int ri = ri0 + it * THREADS;

        float lp10, lp11, p10, p11; sm2(b1[ri], b1[NN + ri], lp10, lp11, p10, p11);
        float lp20, lp21, p20, p21; sm2(b2[ri], b2[NN + ri], lp20, lp21, p20, p21);
        float lp30, lp31, p30, p31; sm2(b3[ri], b3[NN + ri], lp30, lp31, p30, p31);

        int   t  = bt[ri];
        float tf = (float)t;

        float om11 = 1.0f - p11, om10 = 1.0f - p10;
        float om21 = 1.0f - p21, om20 = 1.0f - p20;
        float om31 = 1.0f - p31, om30 = 1.0f - p30;

        float l1 = -tf * om11 * om11 * lp11 - (1.0f - tf) * om10 * om10 * lp10;
        float l2 = -tf * om21 * om21 * lp21 - (1.0f - tf) * om20 * om20 * lp20;
        float l3 = -tf * om31 * om31 * lp31 - (1.0f - tf) * om30 * om30 * lp30;

        float kdl12 = p10 * (lp10 - lp20) + p11 * (lp11 - lp21);
        float kdl21 = p20 * (lp20 - lp10) + p21 * (lp21 - lp11);

        float loss = w * (l1 + l2 + l3) + kdw * (kdl12 + kdl21);

        uint32_t key = f2mono(loss);
        g_keys[(size_t)row * NN + ri]  = key;
        g_loss3[(size_t)row * NN + ri] = l3;
        tcnt += t;

        // warp-aggregated smem histogram (top byte)
        unsigned b  = key >> 24;
        unsigned mm = __match_any_sync(0xffffffffu, b);
        if ((tid & 31) == (__ffs(mm) - 1)) atomicAdd(&sh[b], __popc(mm));
    }
    __syncthreads();
    if (sh[tid]) atomicAdd(&g_hist[row * 256 + tid], sh[tid]);

    // block reduce target count
#pragma unroll
    for (int o = 16; o; o >>= 1) tcnt += __shfl_down_sync(0xffffffffu, tcnt, o);
    __shared__ int swt[8];
    if ((tid & 31) == 0) swt[tid >> 5] = tcnt;
    __syncthreads();
    if (tid == 0) {
        int s = 0;
#pragma unroll
        for (int i = 0; i < 8; i++) s += swt[i];
        atomicAdd(&g_ttotal, (unsigned long long)s);
    }
}

// One warp per row: scan 256 bins, find bucket containing the kneed-th element,
// update prefix/kneed, zero hist for the next pass.
__global__ void k_select(int shift) {
    int warp = threadIdx.x >> 5;
    int lane = threadIdx.x & 31;
    if (warp >= BB) return;
    int row = warp;
    unsigned kneed = (unsigned)g_kneed[row];

    unsigned cum = 0;
    int found_bin = -1;
    unsigned cbefore = 0;

#pragma unroll
    for (int c = 0; c < 8; c++) {
        unsigned v = g_hist[row * 256 + c * 32 + lane];
        unsigned s = v;
#pragma unroll
        for (int off = 1; off < 32; off <<= 1) {
            unsigned n = __shfl_up_sync(0xffffffffu, s, off);
            if (lane >= off) s += n;
        }
        unsigned total = __shfl_sync(0xffffffffu, s, 31);
        if (found_bin < 0) {
            unsigned incl = cum + s;
            unsigned mask = __ballot_sync(0xffffffffu, incl >= kneed);
            if (mask) {
                int fl = __ffs(mask) - 1;
                found_bin = c * 32 + fl;
                unsigned excl_fl = __shfl_sync(0xffffffffu, s - v, fl);
                cbefore = cum + excl_fl;
            }
        }
        cum += total;
        g_hist[row * 256 + c * 32 + lane] = 0u;  // reset for next pass
    }
    if (lane == 0) {
        g_prefix[row] |= ((uint32_t)found_bin) << shift;
        g_kneed[row]   = (int)(kneed - cbefore);
    }
}

// Histogram over next byte, filtered by prefix match on higher bits.
__global__ void __launch_bounds__(THREADS)
k_hist(int shift) {
    __shared__ uint32_t sh[256];
    int tid = threadIdx.x;
    sh[tid] = 0u;
    __syncthreads();

    int row = blockIdx.y;
    uint32_t pfx = g_prefix[row] >> (shift + 8);
    const uint32_t* keys = g_keys + (size_t)row * NN;
    int ri0 = blockIdx.x * TILE + tid;

#pragma unroll
    for (int it = 0; it < ITEMS; it++) {
        uint32_t k = keys[ri0 + it * THREADS];
        bool ok = ((k >> (shift + 8)) == pfx);
        unsigned active = __ballot_sync(0xffffffffu, ok);
        if (ok) {
            unsigned b  = (k >> shift) & 255u;
            unsigned mm = __match_any_sync(active, b);
            if ((tid & 31) == (__ffs(mm) - 1)) atomicAdd(&sh[b], __popc(mm));
        }
    }
    __syncthreads();
    if (sh[tid]) atomicAdd(&g_hist[row * 256 + tid], sh[tid]);
}

// Sum loss3/targets over strictly-below-threshold elements; collect ties.
__global__ void __launch_bounds__(THREADS)
k_sum(const int* __restrict__ tgt) {
    int tid = threadIdx.x;
    int row = blockIdx.y;
    uint32_t thr = g_prefix[row];
    const uint32_t* keys = g_keys  + (size_t)row * NN;
    const float*    l3   = g_loss3 + (size_t)row * NN;
    const int*      bt   = tgt     + (size_t)row * NN;

    double sl = 0.0;
    int    st = 0;
    int ri0 = blockIdx.x * TILE + tid;

#pragma unroll
    for (int it = 0; it < ITEMS; it++) {
        int ri = ri0 + it * THREADS;
        uint32_t k = keys[ri];
        if (k < thr) {
            sl += (double)l3[ri];
            st += bt[ri];
        } else if (k == thr) {
            int p = atomicAdd(&g_eqcount[row], 1);
            if (p < EQCAP) g_eqlist[row * EQCAP + p] = ri;
        }
    }
#pragma unroll
    for (int o = 16; o; o >>= 1) {
        sl += __shfl_down_sync(0xffffffffu, sl, o);
        st += __shfl_down_sync(0xffffffffu, st, o);
    }
    __shared__ double sd[8];
    __shared__ int    si[8];
    if ((tid & 31) == 0) { sd[tid >> 5] = sl; si[tid >> 5] = st; }
    __syncthreads();
    if (tid == 0) {
        double S = 0.0; int T = 0;
#pragma unroll
        for (int i = 0; i < 8; i++) { S += sd[i]; T += si[i]; }
        atomicAdd(&g_sum_l3, S);
        atomicAdd(&g_sum_tsel, (unsigned long long)T);
    }
}

// Resolve ties (take lowest-index equals, matching stable argsort), emit outputs.
__global__ void k_final(const int* __restrict__ tgt, const void* __restrict__ forget,
                        float* __restrict__ out) {
    int tid = threadIdx.x;
    for (int row = 0; row < BB; row++) {
        int m = g_kneed[row];
        int c = min(g_eqcount[row], EQCAP);
        for (int j = tid; j < c; j += blockDim.x) {
            int idx = g_eqlist[row * EQCAP + j];
            int rank = 0;
            for (int q = 0; q < c; q++) rank += (g_eqlist[row * EQCAP + q] < idx) ? 1 : 0;
            if (rank < m) {
                atomicAdd(&g_sum_l3, (double)g_loss3[(size_t)row * NN + idx]);
                atomicAdd(&g_sum_tsel, (unsigned long long)tgt[(size_t)row * NN + idx]);
            }
        }
    }
    __threadfence();
    __syncthreads();
    if (tid == 0) {
        double sl = atomicAdd(&g_sum_l3, 0.0);
        unsigned long long ts = atomicAdd(&g_sum_tsel, 0ull);
        unsigned long long tt = atomicAdd(&g_ttotal, 0ull);
        double rem = 1.0 - read_scalar(forget);
        long long num_rem = (long long)(rem * (double)NN);
        double denom = (double)BB * (double)num_rem;
        out[0] = (float)(sl / denom);                 // loss_out
        out[1] = (float)((double)ts / (double)tt);    // loss_s
    }
}

// ---------------- host entry ----------------
extern "C" void kernel_launch(void* const* d_in, const int* in_sizes, int n_in,
                              void* d_out, int out_size) {
    const float* in1    = (const float*)d_in[0];
    const float* in2    = (const float*)d_in[1];
    const float* in3    = (const float*)d_in[2];
    const int*   tgt    = (const int*)d_in[3];
    const void*  forget = d_in[4];
    const void*  kdw    = d_in[5];
    float* out = (float*)d_out;

    dim3 grid(BLKX, BB);

    k_init<<<1, 256>>>(forget);
    k_compute<<<grid, THREADS>>>(in1, in2, in3, tgt, kdw);
    k_select<<<1, 256>>>(24);
    k_hist<<<grid, THREADS>>>(16);
    k_select<<<1, 256>>>(16);
    k_hist<<<grid, THREADS>>>(8);
    k_select<<<1, 256>>>(8);
    k_hist<<<grid, THREADS>>>(0);
    k_select<<<1, 256>>>(0);
    k_sum<<<grid, THREADS>>>(tgt);
    k_final<<<1, 256>>>(tgt, forget, out);

    (void)in_sizes; (void)n_in; (void)out_size;
}